// round 11
// baseline (speedup 1.0000x reference)
#include <cuda_runtime.h>
#include <cuda_fp16.h>

// SinkhornLoss B=8, N=2048, EPS=0.1, 20 iters — dense fp16 K' fused sweep.
// R11: STRIPE 16->32 (512 sweep blocks, single wave @4 CTA/SM; 4MB partials)
//      + combine_v at 512 blocks / 8 threads-per-column.

#define BATCH 8
#define NDIM  2048
#define LOGN  11
#define SINK_ITERS 20
#define STRIPE 32
#define NSTRIPES (NDIM / STRIPE)        // 64

#define SCALE_EXP 14.426950408889634f   // log2(e)/EPS
#define EPS_LN2   0.06931471805599453f  // EPS*ln(2)

__device__ __half g_K[(size_t)BATCH * NDIM * NDIM];          // 67 MB
__device__ float  g_M[BATCH * NDIM];
__device__ float  g_U[BATCH * NDIM];
__device__ float  g_V[BATCH * NDIM];
__device__ float  g_part[(size_t)BATCH * NSTRIPES * NDIM];   // 4 MB col partials
__device__ float  g_rowpart[BATCH * NDIM];

__device__ __forceinline__ float ex2f(float x) {
    float y; asm("ex2.approx.f32 %0, %1;" : "=f"(y) : "f"(x)); return y;
}
__device__ __forceinline__ float lg2f(float x) {
    float y; asm("lg2.approx.f32 %0, %1;" : "=f"(y) : "f"(x)); return y;
}

__device__ __forceinline__ float block_sum256(float v) {
    __shared__ float sm[8];
    const int lane = threadIdx.x & 31, w = threadIdx.x >> 5;
#pragma unroll
    for (int o = 16; o; o >>= 1) v += __shfl_xor_sync(0xffffffffu, v, o);
    if (lane == 0) sm[w] = v;
    __syncthreads();
    if (w == 0) {
        v = (lane < 8) ? sm[lane] : 0.0f;
#pragma unroll
        for (int o = 4; o; o >>= 1) v += __shfl_xor_sync(0xffffffffu, v, o);
    }
    return v;
}

__global__ void init_v_kernel() {
    g_V[blockIdx.x * 256 + threadIdx.x] = 1.0f;
}

// One block per row: row min, then K'16 = exp2((m - d)*SCALE_EXP).
__global__ void precompute_kernel(const float* __restrict__ D) {
    const int row = blockIdx.x;
    const float4* __restrict__ Dr = (const float4*)(D + (size_t)row * NDIM);
    float4 a = Dr[2 * threadIdx.x];
    float4 b = Dr[2 * threadIdx.x + 1];
    float mn = fminf(fminf(fminf(a.x, a.y), fminf(a.z, a.w)),
                     fminf(fminf(b.x, b.y), fminf(b.z, b.w)));
    __shared__ float sm[8];
    __shared__ float smin;
    const int lane = threadIdx.x & 31, w = threadIdx.x >> 5;
#pragma unroll
    for (int o = 16; o; o >>= 1) mn = fminf(mn, __shfl_xor_sync(0xffffffffu, mn, o));
    if (lane == 0) sm[w] = mn;
    __syncthreads();
    if (threadIdx.x == 0) {
        float m = sm[0];
#pragma unroll
        for (int q = 1; q < 8; q++) m = fminf(m, sm[q]);
        smin = m;
        g_M[row] = m;
    }
    __syncthreads();
    const float m = smin;
    __half2 hs[4];
    hs[0] = __floats2half2_rn(ex2f((m - a.x) * SCALE_EXP), ex2f((m - a.y) * SCALE_EXP));
    hs[1] = __floats2half2_rn(ex2f((m - a.z) * SCALE_EXP), ex2f((m - a.w) * SCALE_EXP));
    hs[2] = __floats2half2_rn(ex2f((m - b.x) * SCALE_EXP), ex2f((m - b.y) * SCALE_EXP));
    hs[3] = __floats2half2_rn(ex2f((m - b.z) * SCALE_EXP), ex2f((m - b.w) * SCALE_EXP));
    ((uint4*)(g_K + (size_t)row * NDIM))[threadIdx.x] = *(const uint4*)hs;
}

// Fused sweep: grid (NSTRIPES, BATCH), 256 threads. Thread t owns cols 8t..8t+7.
// 32-row stripe = 4 stages of 8 rows.
__global__ void __launch_bounds__(256, 4) sweep() {
    const int b = blockIdx.y, stripe = blockIdx.x;
    const int t = threadIdx.x;
    const int lane = t & 31, w = t >> 5;
    const int i0 = stripe * STRIPE;
    const __half* __restrict__ Kb = g_K + ((size_t)b << (2 * LOGN));

    const float4* __restrict__ Vb4 = (const float4*)(g_V + (b << LOGN) + 8 * t);
    float4 va = Vb4[0], vb = Vb4[1];
    const float v_own[8] = { va.x, va.y, va.z, va.w, vb.x, vb.y, vb.z, vb.w };
    float acc[8] = { 0, 0, 0, 0, 0, 0, 0, 0 };

    __shared__ float swp[8][8];   // [warp][row-in-stage]
    __shared__ float s_u[8];

#pragma unroll 1
    for (int s = 0; s < STRIPE / 8; s++) {
        uint4 kr[8];
        float part[8];
#pragma unroll
        for (int r = 0; r < 8; r++) {
            const int i = i0 + s * 8 + r;
            kr[r] = *(const uint4*)(Kb + ((size_t)i << LOGN) + 8 * t);
            float2 f0 = __half22float2(*(__half2*)&kr[r].x);
            float2 f1 = __half22float2(*(__half2*)&kr[r].y);
            float2 f2 = __half22float2(*(__half2*)&kr[r].z);
            float2 f3 = __half22float2(*(__half2*)&kr[r].w);
            part[r] = f0.x * v_own[0] + f0.y * v_own[1] + f1.x * v_own[2] + f1.y * v_own[3]
                    + f2.x * v_own[4] + f2.y * v_own[5] + f3.x * v_own[6] + f3.y * v_own[7];
        }
#pragma unroll
        for (int r = 0; r < 8; r++) {
            float p = part[r];
#pragma unroll
            for (int o = 16; o; o >>= 1) p += __shfl_xor_sync(0xffffffffu, p, o);
            if (lane == 0) swp[w][r] = p;
        }
        __syncthreads();
        if (t < 8) {
            float ssum = swp[0][t] + swp[1][t] + swp[2][t] + swp[3][t]
                       + swp[4][t] + swp[5][t] + swp[6][t] + swp[7][t];
            float u = 1.0f / ssum;
            s_u[t] = u;
            g_U[(b << LOGN) + i0 + s * 8 + t] = u;
        }
        __syncthreads();
#pragma unroll
        for (int r = 0; r < 8; r++) {
            const float u = s_u[r];
            float2 f0 = __half22float2(*(__half2*)&kr[r].x);
            float2 f1 = __half22float2(*(__half2*)&kr[r].y);
            float2 f2 = __half22float2(*(__half2*)&kr[r].z);
            float2 f3 = __half22float2(*(__half2*)&kr[r].w);
            acc[0] += f0.x * u; acc[1] += f0.y * u;
            acc[2] += f1.x * u; acc[3] += f1.y * u;
            acc[4] += f2.x * u; acc[5] += f2.y * u;
            acc[6] += f3.x * u; acc[7] += f3.y * u;
        }
        __syncthreads();   // protect swp/s_u reuse next stage
    }
    float4* P = (float4*)(g_part + (((size_t)(b * NSTRIPES + stripe)) << LOGN) + 8 * t);
    P[0] = make_float4(acc[0], acc[1], acc[2], acc[3]);
    P[1] = make_float4(acc[4], acc[5], acc[6], acc[7]);
}

// v_j = 1/sum_stripes part[j].  512 blocks x 256 thr; 32 cols/block,
// 8 threads per column (each sums NSTRIPES/8 = 8 stripes), shared finish.
__global__ void combine_v() {
    const int bcol = blockIdx.x * 32;          // global column over B*N
    const int b = bcol >> LOGN;
    const int j0 = bcol & (NDIM - 1);
    const int c = threadIdx.x & 31;            // column in group
    const int p = threadIdx.x >> 5;            // partial group 0..7
    const float* __restrict__ P =
        g_part + (((size_t)b * NSTRIPES) << LOGN) + j0 + c;
    float s = 0.0f;
#pragma unroll
    for (int st = p; st < NSTRIPES; st += 8) s += P[(size_t)st << LOGN];
    __shared__ float sh[8][32];
    sh[p][c] = s;
    __syncthreads();
    if (threadIdx.x < 32) {
        float tsum = sh[0][threadIdx.x] + sh[1][threadIdx.x]
                   + sh[2][threadIdx.x] + sh[3][threadIdx.x]
                   + sh[4][threadIdx.x] + sh[5][threadIdx.x]
                   + sh[6][threadIdx.x] + sh[7][threadIdx.x];
        g_V[bcol + threadIdx.x] = 1.0f / tsum;
    }
}

// rowpart_i = u_i * sum_j K' v_j D_ij, with D = m_i - EPS_LN2*log2(K').
__global__ void final_row() {
    const int row = blockIdx.x, b = row >> LOGN;
    const uint4* __restrict__ Kr = (const uint4*)(g_K + (size_t)row * NDIM);
    const float4* __restrict__ Vb = (const float4*)(g_V + (b << LOGN));
    const float m = g_M[row];
    uint4 k = Kr[threadIdx.x];
    float4 v0 = Vb[2 * threadIdx.x];
    float4 v1 = Vb[2 * threadIdx.x + 1];
    float2 f0 = __half22float2(*(__half2*)&k.x);
    float2 f1 = __half22float2(*(__half2*)&k.y);
    float2 f2 = __half22float2(*(__half2*)&k.z);
    float2 f3 = __half22float2(*(__half2*)&k.w);
    float acc = 0.0f;
#define TERM(kp, vv) do {                                    \
        float _d = m - EPS_LN2 * lg2f(kp);                   \
        _d = ((kp) > 0.0f) ? _d : 0.0f;                      \
        acc += (kp) * (vv) * _d;                             \
    } while (0)
    TERM(f0.x, v0.x); TERM(f0.y, v0.y); TERM(f1.x, v0.z); TERM(f1.y, v0.w);
    TERM(f2.x, v1.x); TERM(f2.y, v1.y); TERM(f3.x, v1.z); TERM(f3.y, v1.w);
#undef TERM
    float s = block_sum256(acc);
    if (threadIdx.x == 0) g_rowpart[row] = s * g_U[row];
}

__global__ void final_combine(float* __restrict__ out) {
    float s = 0.0f;
    for (int i = threadIdx.x; i < BATCH * NDIM; i += 256) s += g_rowpart[i];
    s = block_sum256(s);
    if (threadIdx.x == 0) out[0] = s / ((float)NDIM * (float)BATCH);
}

extern "C" void kernel_launch(void* const* d_in, const int* in_sizes, int n_in,
                              void* d_out, int out_size) {
    const float* D = (const float*)d_in[0];
    float* out = (float*)d_out;
    (void)in_sizes; (void)n_in; (void)out_size;

    init_v_kernel<<<BATCH * NDIM / 256, 256>>>();
    precompute_kernel<<<BATCH * NDIM, 256>>>(D);
    for (int t = 0; t < SINK_ITERS; t++) {
        sweep<<<dim3(NSTRIPES, BATCH), 256>>>();
        combine_v<<<BATCH * NDIM / 32, 256>>>();
    }
    final_row<<<BATCH * NDIM, 256>>>();
    final_combine<<<1, 256>>>(out);
}

// round 12
// speedup vs baseline: 1.7148x; 1.7148x over previous
#include <cuda_runtime.h>
#include <cuda_fp16.h>

// SinkhornLoss B=8, N=2048, EPS=0.1, 20 iters — dense fp16 K' fused sweep.
// R12 (from measured-good R10): STRIPE=16, sweep in 4-row stages that decode
// each K element ONCE (t = K*v reused for both row sum and col accumulation;
// col partials are A_j = v_j*C_j, combine does v_new = v_old/sum(A)).
// Reg budget ~58 -> __launch_bounds__(256,4) without spills (R11 lesson).

#define BATCH 8
#define NDIM  2048
#define LOGN  11
#define SINK_ITERS 20
#define STRIPE 16
#define NSTRIPES (NDIM / STRIPE)        // 128

#define SCALE_EXP 14.426950408889634f   // log2(e)/EPS
#define EPS_LN2   0.06931471805599453f  // EPS*ln(2)

__device__ __half g_K[(size_t)BATCH * NDIM * NDIM];          // 67 MB
__device__ float  g_M[BATCH * NDIM];
__device__ float  g_U[BATCH * NDIM];
__device__ float  g_V[BATCH * NDIM];
__device__ float  g_part[(size_t)BATCH * NSTRIPES * NDIM];   // 8 MB col partials
__device__ float  g_rowpart[BATCH * NDIM];

__device__ __forceinline__ float ex2f(float x) {
    float y; asm("ex2.approx.f32 %0, %1;" : "=f"(y) : "f"(x)); return y;
}
__device__ __forceinline__ float lg2f(float x) {
    float y; asm("lg2.approx.f32 %0, %1;" : "=f"(y) : "f"(x)); return y;
}

__device__ __forceinline__ float block_sum256(float v) {
    __shared__ float sm[8];
    const int lane = threadIdx.x & 31, w = threadIdx.x >> 5;
#pragma unroll
    for (int o = 16; o; o >>= 1) v += __shfl_xor_sync(0xffffffffu, v, o);
    if (lane == 0) sm[w] = v;
    __syncthreads();
    if (w == 0) {
        v = (lane < 8) ? sm[lane] : 0.0f;
#pragma unroll
        for (int o = 4; o; o >>= 1) v += __shfl_xor_sync(0xffffffffu, v, o);
    }
    return v;
}

__global__ void init_v_kernel() {
    g_V[blockIdx.x * 256 + threadIdx.x] = 1.0f;
}

// One block per row: row min, then K'16 = exp2((m - d)*SCALE_EXP).
__global__ void precompute_kernel(const float* __restrict__ D) {
    const int row = blockIdx.x;
    const float4* __restrict__ Dr = (const float4*)(D + (size_t)row * NDIM);
    float4 a = Dr[2 * threadIdx.x];
    float4 b = Dr[2 * threadIdx.x + 1];
    float mn = fminf(fminf(fminf(a.x, a.y), fminf(a.z, a.w)),
                     fminf(fminf(b.x, b.y), fminf(b.z, b.w)));
    __shared__ float sm[8];
    __shared__ float smin;
    const int lane = threadIdx.x & 31, w = threadIdx.x >> 5;
#pragma unroll
    for (int o = 16; o; o >>= 1) mn = fminf(mn, __shfl_xor_sync(0xffffffffu, mn, o));
    if (lane == 0) sm[w] = mn;
    __syncthreads();
    if (threadIdx.x == 0) {
        float m = sm[0];
#pragma unroll
        for (int q = 1; q < 8; q++) m = fminf(m, sm[q]);
        smin = m;
        g_M[row] = m;
    }
    __syncthreads();
    const float m = smin;
    __half2 hs[4];
    hs[0] = __floats2half2_rn(ex2f((m - a.x) * SCALE_EXP), ex2f((m - a.y) * SCALE_EXP));
    hs[1] = __floats2half2_rn(ex2f((m - a.z) * SCALE_EXP), ex2f((m - a.w) * SCALE_EXP));
    hs[2] = __floats2half2_rn(ex2f((m - b.x) * SCALE_EXP), ex2f((m - b.y) * SCALE_EXP));
    hs[3] = __floats2half2_rn(ex2f((m - b.z) * SCALE_EXP), ex2f((m - b.w) * SCALE_EXP));
    ((uint4*)(g_K + (size_t)row * NDIM))[threadIdx.x] = *(const uint4*)hs;
}

// Fused sweep: grid (NSTRIPES, BATCH), 256 threads; thread t owns cols 8t..8t+7.
// 16-row stripe = 4 stages of 4 rows; t[r][c] = K*v decoded once per element.
__global__ void __launch_bounds__(256, 4) sweep() {
    const int b = blockIdx.y, stripe = blockIdx.x;
    const int t = threadIdx.x;
    const int lane = t & 31, w = t >> 5;
    const int i0 = stripe * STRIPE;
    const __half* __restrict__ Kb = g_K + ((size_t)b << (2 * LOGN));

    const float4* __restrict__ Vb4 = (const float4*)(g_V + (b << LOGN) + 8 * t);
    float4 va = Vb4[0], vb = Vb4[1];
    const float v_own[8] = { va.x, va.y, va.z, va.w, vb.x, vb.y, vb.z, vb.w };
    float acc[8] = { 0, 0, 0, 0, 0, 0, 0, 0 };

    __shared__ float swp[8][4];   // [warp][row-in-stage]
    __shared__ float s_u[4];

#pragma unroll
    for (int s = 0; s < STRIPE / 4; s++) {
        float tv[4][8];
        float part[4];
#pragma unroll
        for (int r = 0; r < 4; r++) {
            const int i = i0 + s * 4 + r;
            uint4 k = *(const uint4*)(Kb + ((size_t)i << LOGN) + 8 * t);
            float2 f0 = __half22float2(*(__half2*)&k.x);
            float2 f1 = __half22float2(*(__half2*)&k.y);
            float2 f2 = __half22float2(*(__half2*)&k.z);
            float2 f3 = __half22float2(*(__half2*)&k.w);
            tv[r][0] = f0.x * v_own[0]; tv[r][1] = f0.y * v_own[1];
            tv[r][2] = f1.x * v_own[2]; tv[r][3] = f1.y * v_own[3];
            tv[r][4] = f2.x * v_own[4]; tv[r][5] = f2.y * v_own[5];
            tv[r][6] = f3.x * v_own[6]; tv[r][7] = f3.y * v_own[7];
            part[r] = ((tv[r][0] + tv[r][1]) + (tv[r][2] + tv[r][3]))
                    + ((tv[r][4] + tv[r][5]) + (tv[r][6] + tv[r][7]));
        }
#pragma unroll
        for (int r = 0; r < 4; r++) {
            float p = part[r];
#pragma unroll
            for (int o = 16; o; o >>= 1) p += __shfl_xor_sync(0xffffffffu, p, o);
            if (lane == 0) swp[w][r] = p;
        }
        __syncthreads();
        if (t < 4) {
            float ssum = swp[0][t] + swp[1][t] + swp[2][t] + swp[3][t]
                       + swp[4][t] + swp[5][t] + swp[6][t] + swp[7][t];
            float u = 1.0f / ssum;
            s_u[t] = u;
            g_U[(b << LOGN) + i0 + s * 4 + t] = u;
        }
        __syncthreads();
#pragma unroll
        for (int r = 0; r < 4; r++) {
            const float u = s_u[r];
#pragma unroll
            for (int c = 0; c < 8; c++) acc[c] += tv[r][c] * u;
        }
        // no 3rd barrier: next stage's swp/s_u writes are fenced by the two
        // barriers above before any reader can observe them.
    }
    // acc_j = sum_i K_ij v_j u_i = v_j * colsum_j  (A-form partials)
    float4* P = (float4*)(g_part + (((size_t)(b * NSTRIPES + stripe)) << LOGN) + 8 * t);
    P[0] = make_float4(acc[0], acc[1], acc[2], acc[3]);
    P[1] = make_float4(acc[4], acc[5], acc[6], acc[7]);
}

// v_new_j = v_old_j / sum_stripes A_j.  512 blocks x 256 thr; 32 cols/block,
// 8 threads per column (each sums NSTRIPES/8 = 16 stripes), shared finish.
__global__ void combine_v() {
    const int bcol = blockIdx.x * 32;          // global column over B*N
    const int b = bcol >> LOGN;
    const int j0 = bcol & (NDIM - 1);
    const int c = threadIdx.x & 31;            // column in group
    const int p = threadIdx.x >> 5;            // partial group 0..7
    const float* __restrict__ P =
        g_part + (((size_t)b * NSTRIPES) << LOGN) + j0 + c;
    float s = 0.0f;
#pragma unroll
    for (int st = p; st < NSTRIPES; st += 8) s += P[(size_t)st << LOGN];
    __shared__ float sh[8][32];
    sh[p][c] = s;
    __syncthreads();
    if (threadIdx.x < 32) {
        float tsum = sh[0][threadIdx.x] + sh[1][threadIdx.x]
                   + sh[2][threadIdx.x] + sh[3][threadIdx.x]
                   + sh[4][threadIdx.x] + sh[5][threadIdx.x]
                   + sh[6][threadIdx.x] + sh[7][threadIdx.x];
        g_V[bcol + threadIdx.x] = g_V[bcol + threadIdx.x] / tsum;
    }
}

// rowpart_i = u_i * sum_j K' v_j D_ij, with D = m_i - EPS_LN2*log2(K').
__global__ void final_row() {
    const int row = blockIdx.x, b = row >> LOGN;
    const uint4* __restrict__ Kr = (const uint4*)(g_K + (size_t)row * NDIM);
    const float4* __restrict__ Vb = (const float4*)(g_V + (b << LOGN));
    const float m = g_M[row];
    uint4 k = Kr[threadIdx.x];
    float4 v0 = Vb[2 * threadIdx.x];
    float4 v1 = Vb[2 * threadIdx.x + 1];
    float2 f0 = __half22float2(*(__half2*)&k.x);
    float2 f1 = __half22float2(*(__half2*)&k.y);
    float2 f2 = __half22float2(*(__half2*)&k.z);
    float2 f3 = __half22float2(*(__half2*)&k.w);
    float acc = 0.0f;
#define TERM(kp, vv) do {                                    \
        float _d = m - EPS_LN2 * lg2f(kp);                   \
        _d = ((kp) > 0.0f) ? _d : 0.0f;                      \
        acc += (kp) * (vv) * _d;                             \
    } while (0)
    TERM(f0.x, v0.x); TERM(f0.y, v0.y); TERM(f1.x, v0.z); TERM(f1.y, v0.w);
    TERM(f2.x, v1.x); TERM(f2.y, v1.y); TERM(f3.x, v1.z); TERM(f3.y, v1.w);
#undef TERM
    float s = block_sum256(acc);
    if (threadIdx.x == 0) g_rowpart[row] = s * g_U[row];
}

__global__ void final_combine(float* __restrict__ out) {
    float s = 0.0f;
    for (int i = threadIdx.x; i < BATCH * NDIM; i += 256) s += g_rowpart[i];
    s = block_sum256(s);
    if (threadIdx.x == 0) out[0] = s / ((float)NDIM * (float)BATCH);
}

extern "C" void kernel_launch(void* const* d_in, const int* in_sizes, int n_in,
                              void* d_out, int out_size) {
    const float* D = (const float*)d_in[0];
    float* out = (float*)d_out;
    (void)in_sizes; (void)n_in; (void)out_size;

    init_v_kernel<<<BATCH * NDIM / 256, 256>>>();
    precompute_kernel<<<BATCH * NDIM, 256>>>(D);
    for (int t = 0; t < SINK_ITERS; t++) {
        sweep<<<dim3(NSTRIPES, BATCH), 256>>>();
        combine_v<<<BATCH * NDIM / 32, 256>>>();
    }
    final_row<<<BATCH * NDIM, 256>>>();
    final_combine<<<1, 256>>>(out);
}